// round 14
// baseline (speedup 1.0000x reference)
#include <cuda_runtime.h>
#include <cuda_fp16.h>
#include <cstdint>

#define N_NODES 100000
#define N_EDGES 1200000
#define D 64
#define N_LAYERS 3
#define BN 192   // fused output cols: W_O | W_I | W_S
#define NG (BN / 8)              // 24 column-groups of 8
#define BH2L (NG * 4 * 32 * 2)   // 6144 half2 words per layer (fp16 B table)

// ---------------- scratch (static device globals; no allocation) ----------------
__device__ __half g_Xh[3][(size_t)N_NODES * D];   // Xo, Xi, Xs (fp16)
__device__ float g_h[2][(size_t)N_NODES * D];     // ping-pong hidden states
__device__ int   g_counts[N_NODES];               // zero at load; re-zeroed by scanA
__device__ int   g_indptr[N_NODES + 1];
__device__ int   g_cursor[N_NODES];
__device__ int   g_recs[N_EDGES];               // packed: src | et<<17 | dir<<18
__device__ int   g_blockSums[128];
__device__ unsigned g_Bh[N_LAYERS * BH2L];      // fp16 weights, mma-fragment-major
__device__ float g_rO[N_LAYERS][2][D];
__device__ float g_rI[N_LAYERS][2][D];
__device__ float g_rS[N_LAYERS][D];

// ---------------- helpers ----------------
__device__ __forceinline__ unsigned pkh2(float a, float b) {
    __half2 h = __floats2half2_rn(a, b);
    return *reinterpret_cast<unsigned*>(&h);
}
__device__ __forceinline__ void mma_f16(float c[4], unsigned a0, unsigned a1,
                                        unsigned a2, unsigned a3,
                                        unsigned b0, unsigned b1) {
    asm("mma.sync.aligned.m16n8k16.row.col.f32.f16.f16.f32 "
        "{%0,%1,%2,%3}, {%4,%5,%6,%7}, {%8,%9}, {%0,%1,%2,%3};"
        : "+f"(c[0]), "+f"(c[1]), "+f"(c[2]), "+f"(c[3])
        : "r"(a0), "r"(a1), "r"(a2), "r"(a3), "r"(b0), "r"(b1));
}
__device__ __forceinline__ float2 h2f2(unsigned u) {
    __half2 h = *reinterpret_cast<__half2*>(&u);
    return __half22float2(h);
}

// ---------------- transform tile body ----------------
#define SH2W2 52   // half2 words per smem row in epilogue view (48 data + 4 pad)
__device__ __forceinline__ void transform_tile(const float* __restrict__ h,
                                               int layer, int tb,
                                               unsigned char* smem_raw) {
    uint4* sAu4 = reinterpret_cast<uint4*>(smem_raw);      // [16 tiles][33] A frag
    unsigned* sw = reinterpret_cast<unsigned*>(smem_raw);  // word view
    unsigned* sh2 = reinterpret_cast<unsigned*>(smem_raw); // epilogue half2 view

    int tid = threadIdx.x;
    int wid = tid >> 5, lane = tid & 31;
    int gid = lane >> 2, tig = lane & 3;
    int wm = wid & 1, wn = wid >> 1;
    int nh = tb & 1;
    size_t rowbase = (size_t)(tb >> 1) * 64;

    // stage A: coalesced float4 LDG -> fp16 fragment smem
    #pragma unroll
    for (int i = 0; i < 4; i++) {
        int idx = tid + i * 256;          // over 1024 float4 (64 rows x 16)
        int row = idx >> 4, q = idx & 15;
        size_t gr = rowbase + row;
        float4 x = make_float4(0.f, 0.f, 0.f, 0.f);
        if (gr < N_NODES) x = reinterpret_cast<const float4*>(h + gr * D)[q];
        int k16 = q >> 2;
        int tg  = (q << 1) & 3;
        int kh  = (q >> 1) & 1;
        int L   = (row & 7) * 4 + tg;
        int r   = ((row >> 3) & 1) + kh * 2;
        int t   = (row >> 4) * 4 + k16;
        unsigned w = (unsigned)(t * 33 + L) * 4 + r;
        sw[w]     = pkh2(x.x, x.y);
        sw[w + 4] = pkh2(x.z, x.w);
    }
    __syncthreads();

    const uint2* __restrict__ Bh =
        reinterpret_cast<const uint2*>(g_Bh) + (size_t)layer * (BH2L / 2);
    float acc[2][3][4];
    #pragma unroll
    for (int mt = 0; mt < 2; mt++)
        #pragma unroll
        for (int nt = 0; nt < 3; nt++)
            #pragma unroll
            for (int q = 0; q < 4; q++) acc[mt][nt][q] = 0.f;

    #pragma unroll
    for (int k16 = 0; k16 < 4; k16++) {
        uint4 a0 = sAu4[(((wm * 2 + 0) * 4 + k16) * 33) + lane];
        uint4 a1 = sAu4[(((wm * 2 + 1) * 4 + k16) * 33) + lane];
        #pragma unroll
        for (int nt = 0; nt < 3; nt++) {
            int ng = nh * 12 + wn * 3 + nt;
            uint2 b = Bh[((ng * 4 + k16) * 32) + lane];
            mma_f16(acc[0][nt], a0.x, a0.y, a0.z, a0.w, b.x, b.y);
            mma_f16(acc[1][nt], a1.x, a1.y, a1.z, a1.w, b.x, b.y);
        }
    }
    __syncthreads();   // mainloop smem reads done before epilogue reuse

    // epilogue pass 1: acc fragments -> half2 smem (stride 52: conflict-free)
    #pragma unroll
    for (int mt = 0; mt < 2; mt++) {
        #pragma unroll
        for (int half = 0; half < 2; half++) {
            int row = wm * 32 + mt * 16 + half * 8 + gid;
            #pragma unroll
            for (int nt = 0; nt < 3; nt++) {
                int col2 = wn * 12 + nt * 4 + tig;
                float lo = half ? acc[mt][nt][2] : acc[mt][nt][0];
                float hi = half ? acc[mt][nt][3] : acc[mt][nt][1];
                sh2[row * SH2W2 + col2] = pkh2(lo, hi);
            }
        }
    }
    __syncthreads();

    // epilogue pass 2: coalesced STG.128 (8 halves each) to g_Xh
    #pragma unroll
    for (int i = 0; i < 3; i++) {
        int o = tid + i * 256;            // over 768 uint4 slots (64 rows x 12)
        int r = o / 12;
        int q = o % 12;
        size_t gr = rowbase + r;
        if (gr < N_NODES) {
            int c0 = nh * 96 + q * 8;
            int mat = c0 >> 6, cc = c0 & 63;
            uint4 val = *reinterpret_cast<const uint4*>(&sh2[r * SH2W2 + q * 4]);
            *reinterpret_cast<uint4*>(&g_Xh[mat][gr * D + cc]) = val;
        }
    }
}

// ---------------- fused setup: rel (block 0) + prep_b (1..72) + hist (73..) -----
#define WPAD 65
#define NB_PREP 72
#define NB_HIST ((N_EDGES + 1023) / 1024)
__global__ void __launch_bounds__(256) setup_kernel(
        const float* __restrict__ Basis, const float* __restrict__ alpha,
        const float* __restrict__ W_O,  const float* __restrict__ W_I,
        const float* __restrict__ W_S,  const float* __restrict__ W_rel,
        const int* __restrict__ dst) {
    int b = blockIdx.x;
    int tid = threadIdx.x;

    if (b > NB_PREP) {
        // ---- hist: 4 edges per thread, loads batched before atomics ----
        int e = (b - NB_PREP - 1) * 1024 + tid;
        int d0 = (e < N_EDGES) ? dst[e] : -1;
        int d1 = (e + 256 < N_EDGES) ? dst[e + 256] : -1;
        int d2 = (e + 512 < N_EDGES) ? dst[e + 512] : -1;
        int d3 = (e + 768 < N_EDGES) ? dst[e + 768] : -1;
        if (d0 >= 0) atomicAdd(&g_counts[d0], 1);
        if (d1 >= 0) atomicAdd(&g_counts[d1], 1);
        if (d2 >= 0) atomicAdd(&g_counts[d2], 1);
        if (d3 >= 0) atomicAdd(&g_counts[d3], 1);
        return;
    }
    if (b >= 1) {
        // ---- prep_b: fp32 -> fp16 mma-fragment table ----
        int idx = (b - 1) * 256 + tid;
        if (idx >= N_LAYERS * BH2L) return;
        int l = idx / BH2L;
        int s = idx % BH2L;
        int r = s & 1;
        int lane = (s >> 1) & 31;
        int k16 = (s >> 6) & 3;
        int ng = s >> 8;
        int n = ng * 8 + (lane >> 2);
        int k = k16 * 16 + (lane & 3) * 2 + r * 8;
        const float* W = (n < 64) ? W_O : (n < 128) ? W_I : W_S;
        const float* row = W + l * D * D + (n & 63) * D;
        g_Bh[idx] = pkh2(row[k], row[k + 1]);
        return;
    }

    // ---- rel (block 0 only) ----
    __shared__ float sW[2][D * WPAD];
    __shared__ float hr[3][D];
    __shared__ float nhr[3][D];
    int t = tid >> 6;
    int d = tid & 63;

    if (t < 3) {
        float s = 0.f;
        #pragma unroll
        for (int bb = 0; bb < 16; bb++) s += alpha[t * 16 + bb] * Basis[bb * D + d];
        hr[t][d] = s;
    }
    __syncthreads();

    for (int l = 0; l < N_LAYERS; l++) {
        {
            const float4* A = reinterpret_cast<const float4*>(W_O + l * D * D);
            const float4* B = reinterpret_cast<const float4*>(W_I + l * D * D);
            #pragma unroll
            for (int i = 0; i < 4; i++) {
                int idx = tid + i * 256;
                int row = idx >> 4, q = idx & 15;
                float4 a = A[idx], bv = B[idx];
                float* pa = &sW[0][row * WPAD + q * 4];
                float* pb = &sW[1][row * WPAD + q * 4];
                pa[0] = a.x; pa[1] = a.y; pa[2] = a.z; pa[3] = a.w;
                pb[0] = bv.x; pb[1] = bv.y; pb[2] = bv.z; pb[3] = bv.w;
            }
        }
        __syncthreads();
        if (t < 2) {
            float so = 0.f, si = 0.f;
            #pragma unroll
            for (int k = 0; k < D; k++) {
                float hk = hr[t][k];
                so += hk * sW[0][d * WPAD + k];
                si += hk * sW[1][d * WPAD + k];
            }
            g_rO[l][t][d] = so;
            g_rI[l][t][d] = si;
        }
        __syncthreads();
        {
            const float4* A = reinterpret_cast<const float4*>(W_S + l * D * D);
            const float4* B = reinterpret_cast<const float4*>(W_rel + l * D * D);
            #pragma unroll
            for (int i = 0; i < 4; i++) {
                int idx = tid + i * 256;
                int row = idx >> 4, q = idx & 15;
                float4 a = A[idx], bv = B[idx];
                float* pa = &sW[0][row * WPAD + q * 4];
                float* pb = &sW[1][row * WPAD + q * 4];
                pa[0] = a.x; pa[1] = a.y; pa[2] = a.z; pa[3] = a.w;
                pb[0] = bv.x; pb[1] = bv.y; pb[2] = bv.z; pb[3] = bv.w;
            }
        }
        __syncthreads();
        if (t == 3) {
            float ss = 0.f;
            #pragma unroll
            for (int k = 0; k < D; k++) ss += hr[2][k] * sW[0][d * WPAD + k];
            g_rS[l][d] = ss;
        } else {
            float sr = 0.f;
            #pragma unroll
            for (int k = 0; k < D; k++) sr += hr[t][k] * sW[1][d * WPAD + k];
            if (l < N_LAYERS - 1) sr = fmaxf(sr, 0.f);
            nhr[t][d] = sr;
        }
        __syncthreads();
        if (t < 3) hr[t][d] = nhr[t][d];
        __syncthreads();
    }
}

// ---------------- fused scanA + layer-0 transform --------------------------------
// blocks [0,98): block-scan of g_counts (1024 nodes/block, 256 thr x 4) — these
// 98 blocks co-reside with the transform blocks, so the scan hides completely.
// blocks [98, 98+nb): layer-0 transform tiles.
#define NB_SCANA 98
__global__ void __launch_bounds__(256) scanA_t0_kernel(const float* __restrict__ h) {
    __shared__ __align__(16) unsigned char smem_raw[64 * SH2W2 * 4];  // 13.3 KB
    int b = blockIdx.x;
    int tid = threadIdx.x;
    if (b < NB_SCANA) {
        int* ws = reinterpret_cast<int*>(smem_raw);   // 8 ints
        int lane = tid & 31, wid = tid >> 5;
        int base = b * 1024 + tid * 4;
        int v[4];
        #pragma unroll
        for (int j = 0; j < 4; j++) {
            int idx = base + j;
            v[j] = 0;
            if (idx < N_NODES) { v[j] = g_counts[idx]; g_counts[idx] = 0; }
        }
        int s[4];
        s[0] = v[0]; s[1] = s[0] + v[1]; s[2] = s[1] + v[2]; s[3] = s[2] + v[3];
        int t = s[3];
        int inc = t;
        #pragma unroll
        for (int o = 1; o < 32; o <<= 1) {
            int x = __shfl_up_sync(0xffffffffu, inc, o);
            if (lane >= o) inc += x;
        }
        if (lane == 31) ws[wid] = inc;
        __syncthreads();
        if (wid == 0) {
            int wv = (lane < 8) ? ws[lane] : 0;
            int winc = wv;
            #pragma unroll
            for (int o = 1; o < 8; o <<= 1) {
                int x = __shfl_up_sync(0xffffffffu, winc, o);
                if (lane >= o) winc += x;
            }
            if (lane < 8) ws[lane] = winc;   // inclusive warp sums
        }
        __syncthreads();
        int wexcl = (wid > 0) ? ws[wid - 1] : 0;
        int texcl = wexcl + inc - t;
        #pragma unroll
        for (int j = 0; j < 4; j++) {
            int idx = base + j;
            if (idx < N_NODES) g_indptr[idx] = texcl + (j > 0 ? s[j - 1] : 0);
        }
        if (tid == 255) g_blockSums[b] = ws[7];
        return;
    }
    transform_tile(h, 0, b - NB_SCANA, smem_raw);
}

// ---------------- scanB: apply block offsets + init cursor -----------------------
__global__ void __launch_bounds__(256) scanB_kernel() {
    __shared__ int partial[8];
    int b = blockIdx.x;
    int tid = threadIdx.x;
    int lane = tid & 31, wid = tid >> 5;
    int v = (tid < b) ? g_blockSums[tid] : 0;   // b <= 97 < 256
    #pragma unroll
    for (int o = 16; o > 0; o >>= 1) v += __shfl_down_sync(0xffffffffu, v, o);
    if (lane == 0) partial[wid] = v;
    __syncthreads();
    if (wid == 0) {
        int x = (lane < 8) ? partial[lane] : 0;
        #pragma unroll
        for (int o = 4; o > 0; o >>= 1) x += __shfl_down_sync(0xffffffffu, x, o);
        if (lane == 0) partial[0] = x;
    }
    __syncthreads();
    int off = partial[0];
    int base = b * 1024 + tid * 4;
    #pragma unroll
    for (int j = 0; j < 4; j++) {
        int idx = base + j;
        if (idx < N_NODES) {
            int val = g_indptr[idx] + off;
            g_indptr[idx] = val;
            g_cursor[idx] = val;
        }
    }
    if (b == 0 && tid == 0) g_indptr[N_NODES] = N_EDGES;
}

// ---------------- noop: slot filler so ncu (-s 5) captures aggregate_0 -----------
__global__ void noop_kernel() {}

// ---------------- fill: 4 edges/thread, loads batched ----------------------------
__global__ void __launch_bounds__(256) fill_kernel(const int* __restrict__ src,
                                                   const int* __restrict__ dst,
                                                   const int* __restrict__ et,
                                                   const int* __restrict__ dir) {
    int base = blockIdx.x * 1024 + threadIdx.x;
    int e0 = base, e1 = base + 256, e2 = base + 512, e3 = base + 768;
    int d0 = (e0 < N_EDGES) ? dst[e0] : -1;
    int d1 = (e1 < N_EDGES) ? dst[e1] : -1;
    int d2 = (e2 < N_EDGES) ? dst[e2] : -1;
    int d3 = (e3 < N_EDGES) ? dst[e3] : -1;
    int r0 = 0, r1 = 0, r2 = 0, r3 = 0;
    if (d0 >= 0) r0 = src[e0] | (et[e0] << 17) | (dir[e0] << 18);
    if (d1 >= 0) r1 = src[e1] | (et[e1] << 17) | (dir[e1] << 18);
    if (d2 >= 0) r2 = src[e2] | (et[e2] << 17) | (dir[e2] << 18);
    if (d3 >= 0) r3 = src[e3] | (et[e3] << 17) | (dir[e3] << 18);
    int p0 = (d0 >= 0) ? atomicAdd(&g_cursor[d0], 1) : 0;
    int p1 = (d1 >= 0) ? atomicAdd(&g_cursor[d1], 1) : 0;
    int p2 = (d2 >= 0) ? atomicAdd(&g_cursor[d2], 1) : 0;
    int p3 = (d3 >= 0) ? atomicAdd(&g_cursor[d3], 1) : 0;
    if (d0 >= 0) g_recs[p0] = r0;
    if (d1 >= 0) g_recs[p1] = r1;
    if (d2 >= 0) g_recs[p2] = r2;
    if (d3 >= 0) g_recs[p3] = r3;
}

// ---------------- standalone transform (layers 1,2) ------------------------------
__global__ void __launch_bounds__(256) transform_kernel(const float* __restrict__ h,
                                                        int layer) {
    __shared__ __align__(16) unsigned char smem_raw[64 * SH2W2 * 4];  // 13.3 KB
    transform_tile(h, layer, blockIdx.x, smem_raw);
}

// ---------------- aggregation: warp per node, fp16 gathers, 8-edge MLP -----------
__global__ void __launch_bounds__(256) aggregate_kernel(int l, float* __restrict__ hout,
                                                        int do_relu) {
    int warp = (blockIdx.x * blockDim.x + threadIdx.x) >> 5;
    int lane = threadIdx.x & 31;
    if (warp >= N_NODES) return;
    int v = warp;

    const unsigned* Xo = reinterpret_cast<const unsigned*>(&g_Xh[0][0]);
    const unsigned* Xi = reinterpret_cast<const unsigned*>(&g_Xh[1][0]);
    const unsigned* Xs = reinterpret_cast<const unsigned*>(&g_Xh[2][0]);

    float2 acc = h2f2(Xs[(size_t)v * 32 + lane]);

    int beg = g_indptr[v], end = g_indptr[v + 1];
    unsigned cnt = 0;  // 4 packed byte counters: cat = et | dir<<1
    int i = beg;
    for (; i + 7 < end; i += 8) {
        int rc[8];
        #pragma unroll
        for (int j = 0; j < 8; j++) rc[j] = g_recs[i + j];
        float2 m[8];
        #pragma unroll
        for (int j = 0; j < 8; j++) {
            const unsigned* X = (rc[j] & (1 << 18)) ? Xi : Xo;
            m[j] = h2f2(X[(size_t)(rc[j] & 131071) * 32 + lane]);
        }
        #pragma unroll
        for (int j = 0; j < 8; j++) {
            cnt += 1u << (((rc[j] >> 17) & 3) * 8);
            acc.x += m[j].x;
            acc.y += m[j].y;
        }
    }
    for (; i + 3 < end; i += 4) {
        int rec0 = g_recs[i], rec1 = g_recs[i + 1];
        int rec2 = g_recs[i + 2], rec3 = g_recs[i + 3];
        const unsigned* X0 = (rec0 & (1 << 18)) ? Xi : Xo;
        const unsigned* X1 = (rec1 & (1 << 18)) ? Xi : Xo;
        const unsigned* X2 = (rec2 & (1 << 18)) ? Xi : Xo;
        const unsigned* X3 = (rec3 & (1 << 18)) ? Xi : Xo;
        float2 m0 = h2f2(X0[(size_t)(rec0 & 131071) * 32 + lane]);
        float2 m1 = h2f2(X1[(size_t)(rec1 & 131071) * 32 + lane]);
        float2 m2 = h2f2(X2[(size_t)(rec2 & 131071) * 32 + lane]);
        float2 m3 = h2f2(X3[(size_t)(rec3 & 131071) * 32 + lane]);
        cnt += 1u << (((rec0 >> 17) & 3) * 8);
        cnt += 1u << (((rec1 >> 17) & 3) * 8);
        cnt += 1u << (((rec2 >> 17) & 3) * 8);
        cnt += 1u << (((rec3 >> 17) & 3) * 8);
        acc.x += (m0.x + m1.x) + (m2.x + m3.x);
        acc.y += (m0.y + m1.y) + (m2.y + m3.y);
    }
    for (; i < end; i++) {
        int rec0 = g_recs[i];
        const unsigned* X0 = (rec0 & (1 << 18)) ? Xi : Xo;
        float2 m0 = h2f2(X0[(size_t)(rec0 & 131071) * 32 + lane]);
        cnt += 1u << (((rec0 >> 17) & 3) * 8);
        acc.x += m0.x;
        acc.y += m0.y;
    }

    float2 ro0 = reinterpret_cast<const float2*>(g_rO[l][0])[lane];
    float2 ro1 = reinterpret_cast<const float2*>(g_rO[l][1])[lane];
    float2 ri0 = reinterpret_cast<const float2*>(g_rI[l][0])[lane];
    float2 ri1 = reinterpret_cast<const float2*>(g_rI[l][1])[lane];
    float2 rs  = reinterpret_cast<const float2*>(g_rS[l])[lane];
    float n0 = (float)(cnt & 255u);
    float n1 = (float)((cnt >> 8) & 255u);
    float n2 = (float)((cnt >> 16) & 255u);
    float n3 = (float)((cnt >> 24) & 255u);
    acc.x -= n0 * ro0.x + n1 * ro1.x + n2 * ri0.x + n3 * ri1.x + rs.x;
    acc.y -= n0 * ro0.y + n1 * ro1.y + n2 * ri0.y + n3 * ri1.y + rs.y;

    if (do_relu) { acc.x = fmaxf(acc.x, 0.f); acc.y = fmaxf(acc.y, 0.f); }
    reinterpret_cast<float2*>(hout)[(size_t)v * 32 + lane] = acc;
}

// ---------------- launch ----------------
extern "C" void kernel_launch(void* const* d_in, const int* in_sizes, int n_in,
                              void* d_out, int out_size) {
    const float* h_u   = (const float*)d_in[0];
    const float* Basis = (const float*)d_in[1];
    const float* alpha = (const float*)d_in[2];
    const float* W_O   = (const float*)d_in[3];
    const float* W_I   = (const float*)d_in[4];
    const float* W_S   = (const float*)d_in[5];
    const float* W_rel = (const float*)d_in[6];
    const int*   src   = (const int*)d_in[7];
    const int*   dst   = (const int*)d_in[8];
    const int*   et    = (const int*)d_in[9];
    const int*   dir   = (const int*)d_in[10];
    float* out = (float*)d_out;

    void* ph = nullptr;
    cudaGetSymbolAddress(&ph, g_h);
    float* h0 = (float*)ph;
    float* h1 = h0 + (size_t)N_NODES * D;

    int nb_transform = ((N_NODES + 63) / 64) * 2;

    // 1: fused rel + weight-prep + degree-histogram
    setup_kernel<<<1 + NB_PREP + NB_HIST, 256>>>(Basis, alpha, W_O, W_I, W_S,
                                                 W_rel, dst);
    // 2: scanA (98 co-resident blocks) fused with layer-0 transform
    scanA_t0_kernel<<<NB_SCANA + nb_transform, 256>>>(h_u);
    // 3: scanB (apply offsets, init cursor)
    scanB_kernel<<<98, 256>>>();
    // 4: noop — shifts the ncu -s 5 capture slot onto aggregate_0
    noop_kernel<<<1, 32>>>();
    // 5: CSR fill
    fill_kernel<<<(N_EDGES + 1023) / 1024, 256>>>(src, dst, et, dir);

    for (int l = 0; l < N_LAYERS; l++) {
        if (l > 0) {
            const float* hin = (l == 1) ? h0 : h1;
            transform_kernel<<<nb_transform, 256>>>(hin, l);
        }
        float* hout = (l == N_LAYERS - 1) ? out : (l == 0 ? h0 : h1);
        int do_relu = (l < N_LAYERS - 1) ? 1 : 0;
        aggregate_kernel<<<(N_NODES * 32 + 255) / 256, 256>>>(l, hout, do_relu);
    }
}

// round 15
// speedup vs baseline: 1.0168x; 1.0168x over previous
#include <cuda_runtime.h>
#include <cuda_fp16.h>
#include <cstdint>

#define N_NODES 100000
#define N_EDGES 1200000
#define D 64
#define N_LAYERS 3
#define BN 192   // fused output cols: W_O | W_I | W_S
#define NG (BN / 8)              // 24 column-groups of 8
#define BH2L (NG * 4 * 32 * 2)   // 6144 half2 words per layer (fp16 B table)

// ---------------- scratch (static device globals; no allocation) ----------------
__device__ __half g_Xh[3][(size_t)N_NODES * D];   // Xo, Xi, Xs (fp16)
__device__ float g_h[2][(size_t)N_NODES * D];     // ping-pong hidden states
__device__ int   g_counts[N_NODES];               // zero at load; re-zeroed by scan
__device__ int   g_indptr[N_NODES + 1];
__device__ int   g_cursor[N_NODES];
__device__ int   g_recs[N_EDGES];               // packed: src | et<<17 | dir<<18
__device__ int   g_blockSums[128];
__device__ int   g_flags[128];                  // lookback flags; reset by setup
__device__ unsigned g_Bh[N_LAYERS * BH2L];      // fp16 weights, mma-fragment-major
__device__ float g_rO[N_LAYERS][2][D];
__device__ float g_rI[N_LAYERS][2][D];
__device__ float g_rS[N_LAYERS][D];

// ---------------- helpers ----------------
__device__ __forceinline__ unsigned pkh2(float a, float b) {
    __half2 h = __floats2half2_rn(a, b);
    return *reinterpret_cast<unsigned*>(&h);
}
__device__ __forceinline__ void mma_f16(float c[4], unsigned a0, unsigned a1,
                                        unsigned a2, unsigned a3,
                                        unsigned b0, unsigned b1) {
    asm("mma.sync.aligned.m16n8k16.row.col.f32.f16.f16.f32 "
        "{%0,%1,%2,%3}, {%4,%5,%6,%7}, {%8,%9}, {%0,%1,%2,%3};"
        : "+f"(c[0]), "+f"(c[1]), "+f"(c[2]), "+f"(c[3])
        : "r"(a0), "r"(a1), "r"(a2), "r"(a3), "r"(b0), "r"(b1));
}
__device__ __forceinline__ float2 h2f2(unsigned u) {
    __half2 h = *reinterpret_cast<__half2*>(&u);
    return __half22float2(h);
}

// ---------------- transform tile body ----------------
#define SH2W2 52   // half2 words per smem row in epilogue view (48 data + 4 pad)
__device__ __forceinline__ void transform_tile(const float* __restrict__ h,
                                               int layer, int tb,
                                               unsigned char* smem_raw) {
    uint4* sAu4 = reinterpret_cast<uint4*>(smem_raw);      // [16 tiles][33] A frag
    unsigned* sw = reinterpret_cast<unsigned*>(smem_raw);  // word view
    unsigned* sh2 = reinterpret_cast<unsigned*>(smem_raw); // epilogue half2 view

    int tid = threadIdx.x;
    int wid = tid >> 5, lane = tid & 31;
    int gid = lane >> 2, tig = lane & 3;
    int wm = wid & 1, wn = wid >> 1;
    int nh = tb & 1;
    size_t rowbase = (size_t)(tb >> 1) * 64;

    // stage A: coalesced float4 LDG -> fp16 fragment smem
    #pragma unroll
    for (int i = 0; i < 4; i++) {
        int idx = tid + i * 256;          // over 1024 float4 (64 rows x 16)
        int row = idx >> 4, q = idx & 15;
        size_t gr = rowbase + row;
        float4 x = make_float4(0.f, 0.f, 0.f, 0.f);
        if (gr < N_NODES) x = reinterpret_cast<const float4*>(h + gr * D)[q];
        int k16 = q >> 2;
        int tg  = (q << 1) & 3;
        int kh  = (q >> 1) & 1;
        int L   = (row & 7) * 4 + tg;
        int r   = ((row >> 3) & 1) + kh * 2;
        int t   = (row >> 4) * 4 + k16;
        unsigned w = (unsigned)(t * 33 + L) * 4 + r;
        sw[w]     = pkh2(x.x, x.y);
        sw[w + 4] = pkh2(x.z, x.w);
    }
    __syncthreads();

    const uint2* __restrict__ Bh =
        reinterpret_cast<const uint2*>(g_Bh) + (size_t)layer * (BH2L / 2);
    float acc[2][3][4];
    #pragma unroll
    for (int mt = 0; mt < 2; mt++)
        #pragma unroll
        for (int nt = 0; nt < 3; nt++)
            #pragma unroll
            for (int q = 0; q < 4; q++) acc[mt][nt][q] = 0.f;

    #pragma unroll
    for (int k16 = 0; k16 < 4; k16++) {
        uint4 a0 = sAu4[(((wm * 2 + 0) * 4 + k16) * 33) + lane];
        uint4 a1 = sAu4[(((wm * 2 + 1) * 4 + k16) * 33) + lane];
        #pragma unroll
        for (int nt = 0; nt < 3; nt++) {
            int ng = nh * 12 + wn * 3 + nt;
            uint2 b = Bh[((ng * 4 + k16) * 32) + lane];
            mma_f16(acc[0][nt], a0.x, a0.y, a0.z, a0.w, b.x, b.y);
            mma_f16(acc[1][nt], a1.x, a1.y, a1.z, a1.w, b.x, b.y);
        }
    }
    __syncthreads();   // mainloop smem reads done before epilogue reuse

    // epilogue pass 1: acc fragments -> half2 smem (stride 52: conflict-free)
    #pragma unroll
    for (int mt = 0; mt < 2; mt++) {
        #pragma unroll
        for (int half = 0; half < 2; half++) {
            int row = wm * 32 + mt * 16 + half * 8 + gid;
            #pragma unroll
            for (int nt = 0; nt < 3; nt++) {
                int col2 = wn * 12 + nt * 4 + tig;
                float lo = half ? acc[mt][nt][2] : acc[mt][nt][0];
                float hi = half ? acc[mt][nt][3] : acc[mt][nt][1];
                sh2[row * SH2W2 + col2] = pkh2(lo, hi);
            }
        }
    }
    __syncthreads();

    // epilogue pass 2: coalesced STG.128 (8 halves each) to g_Xh
    #pragma unroll
    for (int i = 0; i < 3; i++) {
        int o = tid + i * 256;            // over 768 uint4 slots (64 rows x 12)
        int r = o / 12;
        int q = o % 12;
        size_t gr = rowbase + r;
        if (gr < N_NODES) {
            int c0 = nh * 96 + q * 8;
            int mat = c0 >> 6, cc = c0 & 63;
            uint4 val = *reinterpret_cast<const uint4*>(&sh2[r * SH2W2 + q * 4]);
            *reinterpret_cast<uint4*>(&g_Xh[mat][gr * D + cc]) = val;
        }
    }
}

// ---------------- fused setup: rel (block 0) + prep_b (1..72) + hist (73..) -----
#define WPAD 65
#define NB_PREP 72
#define NB_HIST ((N_EDGES + 1023) / 1024)
__global__ void __launch_bounds__(256) setup_kernel(
        const float* __restrict__ Basis, const float* __restrict__ alpha,
        const float* __restrict__ W_O,  const float* __restrict__ W_I,
        const float* __restrict__ W_S,  const float* __restrict__ W_rel,
        const int* __restrict__ dst) {
    int b = blockIdx.x;
    int tid = threadIdx.x;

    if (b > NB_PREP) {
        // ---- hist: 4 edges per thread, loads batched before atomics ----
        int e = (b - NB_PREP - 1) * 1024 + tid;
        int d0 = (e < N_EDGES) ? dst[e] : -1;
        int d1 = (e + 256 < N_EDGES) ? dst[e + 256] : -1;
        int d2 = (e + 512 < N_EDGES) ? dst[e + 512] : -1;
        int d3 = (e + 768 < N_EDGES) ? dst[e + 768] : -1;
        if (d0 >= 0) atomicAdd(&g_counts[d0], 1);
        if (d1 >= 0) atomicAdd(&g_counts[d1], 1);
        if (d2 >= 0) atomicAdd(&g_counts[d2], 1);
        if (d3 >= 0) atomicAdd(&g_counts[d3], 1);
        return;
    }
    if (b >= 1) {
        // block 1 also resets lookback flags for this replay
        if (b == 1 && tid < 128) g_flags[tid] = 0;
        // ---- prep_b: fp32 -> fp16 mma-fragment table ----
        int idx = (b - 1) * 256 + tid;
        if (idx >= N_LAYERS * BH2L) return;
        int l = idx / BH2L;
        int s = idx % BH2L;
        int r = s & 1;
        int lane = (s >> 1) & 31;
        int k16 = (s >> 6) & 3;
        int ng = s >> 8;
        int n = ng * 8 + (lane >> 2);
        int k = k16 * 16 + (lane & 3) * 2 + r * 8;
        const float* W = (n < 64) ? W_O : (n < 128) ? W_I : W_S;
        const float* row = W + l * D * D + (n & 63) * D;
        g_Bh[idx] = pkh2(row[k], row[k + 1]);
        return;
    }

    // ---- rel (block 0 only) ----
    __shared__ float sW[2][D * WPAD];
    __shared__ float hr[3][D];
    __shared__ float nhr[3][D];
    int t = tid >> 6;
    int d = tid & 63;

    if (t < 3) {
        float s = 0.f;
        #pragma unroll
        for (int bb = 0; bb < 16; bb++) s += alpha[t * 16 + bb] * Basis[bb * D + d];
        hr[t][d] = s;
    }
    __syncthreads();

    for (int l = 0; l < N_LAYERS; l++) {
        {
            const float4* A = reinterpret_cast<const float4*>(W_O + l * D * D);
            const float4* B = reinterpret_cast<const float4*>(W_I + l * D * D);
            #pragma unroll
            for (int i = 0; i < 4; i++) {
                int idx = tid + i * 256;
                int row = idx >> 4, q = idx & 15;
                float4 a = A[idx], bv = B[idx];
                float* pa = &sW[0][row * WPAD + q * 4];
                float* pb = &sW[1][row * WPAD + q * 4];
                pa[0] = a.x; pa[1] = a.y; pa[2] = a.z; pa[3] = a.w;
                pb[0] = bv.x; pb[1] = bv.y; pb[2] = bv.z; pb[3] = bv.w;
            }
        }
        __syncthreads();
        if (t < 2) {
            float so = 0.f, si = 0.f;
            #pragma unroll
            for (int k = 0; k < D; k++) {
                float hk = hr[t][k];
                so += hk * sW[0][d * WPAD + k];
                si += hk * sW[1][d * WPAD + k];
            }
            g_rO[l][t][d] = so;
            g_rI[l][t][d] = si;
        }
        __syncthreads();
        {
            const float4* A = reinterpret_cast<const float4*>(W_S + l * D * D);
            const float4* B = reinterpret_cast<const float4*>(W_rel + l * D * D);
            #pragma unroll
            for (int i = 0; i < 4; i++) {
                int idx = tid + i * 256;
                int row = idx >> 4, q = idx & 15;
                float4 a = A[idx], bv = B[idx];
                float* pa = &sW[0][row * WPAD + q * 4];
                float* pb = &sW[1][row * WPAD + q * 4];
                pa[0] = a.x; pa[1] = a.y; pa[2] = a.z; pa[3] = a.w;
                pb[0] = bv.x; pb[1] = bv.y; pb[2] = bv.z; pb[3] = bv.w;
            }
        }
        __syncthreads();
        if (t == 3) {
            float ss = 0.f;
            #pragma unroll
            for (int k = 0; k < D; k++) ss += hr[2][k] * sW[0][d * WPAD + k];
            g_rS[l][d] = ss;
        } else {
            float sr = 0.f;
            #pragma unroll
            for (int k = 0; k < D; k++) sr += hr[t][k] * sW[1][d * WPAD + k];
            if (l < N_LAYERS - 1) sr = fmaxf(sr, 0.f);
            nhr[t][d] = sr;
        }
        __syncthreads();
        if (t < 3) hr[t][d] = nhr[t][d];
        __syncthreads();
    }
}

// ---------------- fused single-pass scan (decoupled lookback) + layer-0 transform
// blocks [0,98): scan 1024 nodes each; publish block sum with release flag, spin
// on predecessors' flags, then write FINAL indptr + cursor. All 98 scan blocks
// are wave-1 co-resident (grid head), so spins always terminate.
// blocks [98, ...): layer-0 transform tiles.
#define NB_SCANA 98
__global__ void __launch_bounds__(256) scanA_t0_kernel(const float* __restrict__ h) {
    __shared__ __align__(16) unsigned char smem_raw[64 * SH2W2 * 4];  // 13.3 KB
    int b = blockIdx.x;
    int tid = threadIdx.x;
    if (b < NB_SCANA) {
        int* sm = reinterpret_cast<int*>(smem_raw);
        int* ws = sm;            // 8 warp-inclusive sums
        int* partial = sm + 8;   // 8 lookback partials
        int lane = tid & 31, wid = tid >> 5;
        int base = b * 1024 + tid * 4;
        int v[4];
        #pragma unroll
        for (int j = 0; j < 4; j++) {
            int idx = base + j;
            v[j] = 0;
            if (idx < N_NODES) { v[j] = g_counts[idx]; g_counts[idx] = 0; }
        }
        int s[4];
        s[0] = v[0]; s[1] = s[0] + v[1]; s[2] = s[1] + v[2]; s[3] = s[2] + v[3];
        int t = s[3];
        int inc = t;
        #pragma unroll
        for (int o = 1; o < 32; o <<= 1) {
            int x = __shfl_up_sync(0xffffffffu, inc, o);
            if (lane >= o) inc += x;
        }
        if (lane == 31) ws[wid] = inc;
        __syncthreads();
        if (wid == 0) {
            int wv = (lane < 8) ? ws[lane] : 0;
            int winc = wv;
            #pragma unroll
            for (int o = 1; o < 8; o <<= 1) {
                int x = __shfl_up_sync(0xffffffffu, winc, o);
                if (lane >= o) winc += x;
            }
            if (lane < 8) ws[lane] = winc;   // inclusive warp sums
        }
        __syncthreads();
        // publish block total ASAP (release: fence then flag)
        if (tid == 0) {
            g_blockSums[b] = ws[7];
            __threadfence();
            *((volatile int*)&g_flags[b]) = 1;
        }
        int wexcl = (wid > 0) ? ws[wid - 1] : 0;
        int texcl = wexcl + inc - t;
        // decoupled lookback: thread p (< b) waits for block p's sum
        int myv = 0;
        if (tid < b) {
            volatile int* vf = (volatile int*)g_flags;
            while (vf[tid] == 0) {}
            __threadfence();
            myv = g_blockSums[tid];
        }
        #pragma unroll
        for (int o = 16; o > 0; o >>= 1) myv += __shfl_down_sync(0xffffffffu, myv, o);
        if (lane == 0) partial[wid] = myv;
        __syncthreads();
        if (wid == 0) {
            int x = (lane < 8) ? partial[lane] : 0;
            #pragma unroll
            for (int o = 4; o > 0; o >>= 1) x += __shfl_down_sync(0xffffffffu, x, o);
            if (lane == 0) partial[0] = x;
        }
        __syncthreads();
        int off = partial[0];
        #pragma unroll
        for (int j = 0; j < 4; j++) {
            int idx = base + j;
            if (idx < N_NODES) {
                int val = off + texcl + (j > 0 ? s[j - 1] : 0);
                g_indptr[idx] = val;
                g_cursor[idx] = val;
            }
        }
        if (b == 0 && tid == 0) g_indptr[N_NODES] = N_EDGES;
        return;
    }
    transform_tile(h, 0, b - NB_SCANA, smem_raw);
}

// ---------------- fill: 4 edges/thread, loads batched ----------------------------
__global__ void __launch_bounds__(256) fill_kernel(const int* __restrict__ src,
                                                   const int* __restrict__ dst,
                                                   const int* __restrict__ et,
                                                   const int* __restrict__ dir) {
    int base = blockIdx.x * 1024 + threadIdx.x;
    int e0 = base, e1 = base + 256, e2 = base + 512, e3 = base + 768;
    int d0 = (e0 < N_EDGES) ? dst[e0] : -1;
    int d1 = (e1 < N_EDGES) ? dst[e1] : -1;
    int d2 = (e2 < N_EDGES) ? dst[e2] : -1;
    int d3 = (e3 < N_EDGES) ? dst[e3] : -1;
    int r0 = 0, r1 = 0, r2 = 0, r3 = 0;
    if (d0 >= 0) r0 = src[e0] | (et[e0] << 17) | (dir[e0] << 18);
    if (d1 >= 0) r1 = src[e1] | (et[e1] << 17) | (dir[e1] << 18);
    if (d2 >= 0) r2 = src[e2] | (et[e2] << 17) | (dir[e2] << 18);
    if (d3 >= 0) r3 = src[e3] | (et[e3] << 17) | (dir[e3] << 18);
    int p0 = (d0 >= 0) ? atomicAdd(&g_cursor[d0], 1) : 0;
    int p1 = (d1 >= 0) ? atomicAdd(&g_cursor[d1], 1) : 0;
    int p2 = (d2 >= 0) ? atomicAdd(&g_cursor[d2], 1) : 0;
    int p3 = (d3 >= 0) ? atomicAdd(&g_cursor[d3], 1) : 0;
    if (d0 >= 0) g_recs[p0] = r0;
    if (d1 >= 0) g_recs[p1] = r1;
    if (d2 >= 0) g_recs[p2] = r2;
    if (d3 >= 0) g_recs[p3] = r3;
}

// ---------------- standalone transform (layers 1,2) ------------------------------
__global__ void __launch_bounds__(256) transform_kernel(const float* __restrict__ h,
                                                        int layer) {
    __shared__ __align__(16) unsigned char smem_raw[64 * SH2W2 * 4];  // 13.3 KB
    transform_tile(h, layer, blockIdx.x, smem_raw);
}

// ---------------- aggregation: warp per node, fp16 gathers, 8-edge MLP -----------
__global__ void __launch_bounds__(256) aggregate_kernel(int l, float* __restrict__ hout,
                                                        int do_relu) {
    int warp = (blockIdx.x * blockDim.x + threadIdx.x) >> 5;
    int lane = threadIdx.x & 31;
    if (warp >= N_NODES) return;
    int v = warp;

    const unsigned* Xo = reinterpret_cast<const unsigned*>(&g_Xh[0][0]);
    const unsigned* Xi = reinterpret_cast<const unsigned*>(&g_Xh[1][0]);
    const unsigned* Xs = reinterpret_cast<const unsigned*>(&g_Xh[2][0]);

    float2 acc = h2f2(Xs[(size_t)v * 32 + lane]);

    int beg = g_indptr[v], end = g_indptr[v + 1];
    unsigned cnt = 0;  // 4 packed byte counters: cat = et | dir<<1
    int i = beg;
    for (; i + 7 < end; i += 8) {
        int rc[8];
        #pragma unroll
        for (int j = 0; j < 8; j++) rc[j] = g_recs[i + j];
        float2 m[8];
        #pragma unroll
        for (int j = 0; j < 8; j++) {
            const unsigned* X = (rc[j] & (1 << 18)) ? Xi : Xo;
            m[j] = h2f2(X[(size_t)(rc[j] & 131071) * 32 + lane]);
        }
        #pragma unroll
        for (int j = 0; j < 8; j++) {
            cnt += 1u << (((rc[j] >> 17) & 3) * 8);
            acc.x += m[j].x;
            acc.y += m[j].y;
        }
    }
    for (; i + 3 < end; i += 4) {
        int rec0 = g_recs[i], rec1 = g_recs[i + 1];
        int rec2 = g_recs[i + 2], rec3 = g_recs[i + 3];
        const unsigned* X0 = (rec0 & (1 << 18)) ? Xi : Xo;
        const unsigned* X1 = (rec1 & (1 << 18)) ? Xi : Xo;
        const unsigned* X2 = (rec2 & (1 << 18)) ? Xi : Xo;
        const unsigned* X3 = (rec3 & (1 << 18)) ? Xi : Xo;
        float2 m0 = h2f2(X0[(size_t)(rec0 & 131071) * 32 + lane]);
        float2 m1 = h2f2(X1[(size_t)(rec1 & 131071) * 32 + lane]);
        float2 m2 = h2f2(X2[(size_t)(rec2 & 131071) * 32 + lane]);
        float2 m3 = h2f2(X3[(size_t)(rec3 & 131071) * 32 + lane]);
        cnt += 1u << (((rec0 >> 17) & 3) * 8);
        cnt += 1u << (((rec1 >> 17) & 3) * 8);
        cnt += 1u << (((rec2 >> 17) & 3) * 8);
        cnt += 1u << (((rec3 >> 17) & 3) * 8);
        acc.x += (m0.x + m1.x) + (m2.x + m3.x);
        acc.y += (m0.y + m1.y) + (m2.y + m3.y);
    }
    for (; i < end; i++) {
        int rec0 = g_recs[i];
        const unsigned* X0 = (rec0 & (1 << 18)) ? Xi : Xo;
        float2 m0 = h2f2(X0[(size_t)(rec0 & 131071) * 32 + lane]);
        cnt += 1u << (((rec0 >> 17) & 3) * 8);
        acc.x += m0.x;
        acc.y += m0.y;
    }

    float2 ro0 = reinterpret_cast<const float2*>(g_rO[l][0])[lane];
    float2 ro1 = reinterpret_cast<const float2*>(g_rO[l][1])[lane];
    float2 ri0 = reinterpret_cast<const float2*>(g_rI[l][0])[lane];
    float2 ri1 = reinterpret_cast<const float2*>(g_rI[l][1])[lane];
    float2 rs  = reinterpret_cast<const float2*>(g_rS[l])[lane];
    float n0 = (float)(cnt & 255u);
    float n1 = (float)((cnt >> 8) & 255u);
    float n2 = (float)((cnt >> 16) & 255u);
    float n3 = (float)((cnt >> 24) & 255u);
    acc.x -= n0 * ro0.x + n1 * ro1.x + n2 * ri0.x + n3 * ri1.x + rs.x;
    acc.y -= n0 * ro0.y + n1 * ro1.y + n2 * ri0.y + n3 * ri1.y + rs.y;

    if (do_relu) { acc.x = fmaxf(acc.x, 0.f); acc.y = fmaxf(acc.y, 0.f); }
    reinterpret_cast<float2*>(hout)[(size_t)v * 32 + lane] = acc;
}

// ---------------- launch ----------------
extern "C" void kernel_launch(void* const* d_in, const int* in_sizes, int n_in,
                              void* d_out, int out_size) {
    const float* h_u   = (const float*)d_in[0];
    const float* Basis = (const float*)d_in[1];
    const float* alpha = (const float*)d_in[2];
    const float* W_O   = (const float*)d_in[3];
    const float* W_I   = (const float*)d_in[4];
    const float* W_S   = (const float*)d_in[5];
    const float* W_rel = (const float*)d_in[6];
    const int*   src   = (const int*)d_in[7];
    const int*   dst   = (const int*)d_in[8];
    const int*   et    = (const int*)d_in[9];
    const int*   dir   = (const int*)d_in[10];
    float* out = (float*)d_out;

    void* ph = nullptr;
    cudaGetSymbolAddress(&ph, g_h);
    float* h0 = (float*)ph;
    float* h1 = h0 + (size_t)N_NODES * D;

    int nb_transform = ((N_NODES + 63) / 64) * 2;

    // 1: fused rel + weight-prep + degree-histogram (+ flag reset)
    setup_kernel<<<1 + NB_PREP + NB_HIST, 256>>>(Basis, alpha, W_O, W_I, W_S,
                                                 W_rel, dst);
    // 2: single-pass scan (lookback) fused with layer-0 transform
    scanA_t0_kernel<<<NB_SCANA + nb_transform, 256>>>(h_u);
    // 3: CSR fill
    fill_kernel<<<(N_EDGES + 1023) / 1024, 256>>>(src, dst, et, dir);

    for (int l = 0; l < N_LAYERS; l++) {
        if (l > 0) {
            const float* hin = (l == 1) ? h0 : h1;
            transform_kernel<<<nb_transform, 256>>>(hin, l);
        }
        float* hout = (l == N_LAYERS - 1) ? out : (l == 0 ? h0 : h1);
        int do_relu = (l < N_LAYERS - 1) ? 1 : 0;
        aggregate_kernel<<<(N_NODES * 32 + 255) / 256, 256>>>(l, hout, do_relu);
    }
}

// round 16
// speedup vs baseline: 1.0390x; 1.0218x over previous
#include <cuda_runtime.h>
#include <cuda_fp16.h>
#include <cstdint>

#define N_NODES 100000
#define N_EDGES 1200000
#define D 64
#define N_LAYERS 3
#define BN 192   // fused output cols: W_O | W_I | W_S
#define NG (BN / 8)              // 24 column-groups of 8
#define BH2L (NG * 4 * 32 * 2)   // 6144 half2 words per layer (fp16 B table)

// ---------------- scratch (static device globals; no allocation) ----------------
__device__ __half g_Xh[3][(size_t)N_NODES * D];   // Xo, Xi, Xs (fp16)
__device__ float g_h[2][(size_t)N_NODES * D];     // ping-pong hidden states
__device__ int   g_counts[N_NODES];               // zero at load; re-zeroed by scan
__device__ int   g_indptr[N_NODES + 1];
__device__ int   g_cursor[N_NODES];
__device__ int   g_recs[N_EDGES];   // packed: (src + dir*N) | (cat*8)<<18
__device__ int   g_blockSums[128];
__device__ int   g_flags[128];                  // lookback flags; reset by setup
__device__ unsigned g_Bh[N_LAYERS * BH2L];      // fp16 weights, mma-fragment-major
__device__ float g_rO[N_LAYERS][2][D];
__device__ float g_rI[N_LAYERS][2][D];
__device__ float g_rS[N_LAYERS][D];

// ---------------- helpers ----------------
__device__ __forceinline__ unsigned pkh2(float a, float b) {
    __half2 h = __floats2half2_rn(a, b);
    return *reinterpret_cast<unsigned*>(&h);
}
__device__ __forceinline__ void mma_f16(float c[4], unsigned a0, unsigned a1,
                                        unsigned a2, unsigned a3,
                                        unsigned b0, unsigned b1) {
    asm("mma.sync.aligned.m16n8k16.row.col.f32.f16.f16.f32 "
        "{%0,%1,%2,%3}, {%4,%5,%6,%7}, {%8,%9}, {%0,%1,%2,%3};"
        : "+f"(c[0]), "+f"(c[1]), "+f"(c[2]), "+f"(c[3])
        : "r"(a0), "r"(a1), "r"(a2), "r"(a3), "r"(b0), "r"(b1));
}
__device__ __forceinline__ float2 h2f2(unsigned u) {
    __half2 h = *reinterpret_cast<__half2*>(&u);
    return __half22float2(h);
}

// ---------------- transform tile body ----------------
#define SH2W2 52   // half2 words per smem row in epilogue view (48 data + 4 pad)
__device__ __forceinline__ void transform_tile(const float* __restrict__ h,
                                               int layer, int tb,
                                               unsigned char* smem_raw) {
    uint4* sAu4 = reinterpret_cast<uint4*>(smem_raw);      // [16 tiles][33] A frag
    unsigned* sw = reinterpret_cast<unsigned*>(smem_raw);  // word view
    unsigned* sh2 = reinterpret_cast<unsigned*>(smem_raw); // epilogue half2 view

    int tid = threadIdx.x;
    int wid = tid >> 5, lane = tid & 31;
    int gid = lane >> 2, tig = lane & 3;
    int wm = wid & 1, wn = wid >> 1;
    int nh = tb & 1;
    size_t rowbase = (size_t)(tb >> 1) * 64;

    // stage A: coalesced float4 LDG -> fp16 fragment smem
    #pragma unroll
    for (int i = 0; i < 4; i++) {
        int idx = tid + i * 256;          // over 1024 float4 (64 rows x 16)
        int row = idx >> 4, q = idx & 15;
        size_t gr = rowbase + row;
        float4 x = make_float4(0.f, 0.f, 0.f, 0.f);
        if (gr < N_NODES) x = reinterpret_cast<const float4*>(h + gr * D)[q];
        int k16 = q >> 2;
        int tg  = (q << 1) & 3;
        int kh  = (q >> 1) & 1;
        int L   = (row & 7) * 4 + tg;
        int r   = ((row >> 3) & 1) + kh * 2;
        int t   = (row >> 4) * 4 + k16;
        unsigned w = (unsigned)(t * 33 + L) * 4 + r;
        sw[w]     = pkh2(x.x, x.y);
        sw[w + 4] = pkh2(x.z, x.w);
    }
    __syncthreads();

    const uint2* __restrict__ Bh =
        reinterpret_cast<const uint2*>(g_Bh) + (size_t)layer * (BH2L / 2);
    float acc[2][3][4];
    #pragma unroll
    for (int mt = 0; mt < 2; mt++)
        #pragma unroll
        for (int nt = 0; nt < 3; nt++)
            #pragma unroll
            for (int q = 0; q < 4; q++) acc[mt][nt][q] = 0.f;

    #pragma unroll
    for (int k16 = 0; k16 < 4; k16++) {
        uint4 a0 = sAu4[(((wm * 2 + 0) * 4 + k16) * 33) + lane];
        uint4 a1 = sAu4[(((wm * 2 + 1) * 4 + k16) * 33) + lane];
        #pragma unroll
        for (int nt = 0; nt < 3; nt++) {
            int ng = nh * 12 + wn * 3 + nt;
            uint2 b = Bh[((ng * 4 + k16) * 32) + lane];
            mma_f16(acc[0][nt], a0.x, a0.y, a0.z, a0.w, b.x, b.y);
            mma_f16(acc[1][nt], a1.x, a1.y, a1.z, a1.w, b.x, b.y);
        }
    }
    __syncthreads();   // mainloop smem reads done before epilogue reuse

    // epilogue pass 1: acc fragments -> half2 smem (stride 52: conflict-free)
    #pragma unroll
    for (int mt = 0; mt < 2; mt++) {
        #pragma unroll
        for (int half = 0; half < 2; half++) {
            int row = wm * 32 + mt * 16 + half * 8 + gid;
            #pragma unroll
            for (int nt = 0; nt < 3; nt++) {
                int col2 = wn * 12 + nt * 4 + tig;
                float lo = half ? acc[mt][nt][2] : acc[mt][nt][0];
                float hi = half ? acc[mt][nt][3] : acc[mt][nt][1];
                sh2[row * SH2W2 + col2] = pkh2(lo, hi);
            }
        }
    }
    __syncthreads();

    // epilogue pass 2: coalesced STG.128 (8 halves each) to g_Xh
    #pragma unroll
    for (int i = 0; i < 3; i++) {
        int o = tid + i * 256;            // over 768 uint4 slots (64 rows x 12)
        int r = o / 12;
        int q = o % 12;
        size_t gr = rowbase + r;
        if (gr < N_NODES) {
            int c0 = nh * 96 + q * 8;
            int mat = c0 >> 6, cc = c0 & 63;
            uint4 val = *reinterpret_cast<const uint4*>(&sh2[r * SH2W2 + q * 4]);
            *reinterpret_cast<uint4*>(&g_Xh[mat][gr * D + cc]) = val;
        }
    }
}

// ---------------- fused setup: rel (block 0) + prep_b (1..72) + hist (73..) -----
#define WPAD 65
#define NB_PREP 72
#define NB_HIST ((N_EDGES + 1023) / 1024)
__global__ void __launch_bounds__(256) setup_kernel(
        const float* __restrict__ Basis, const float* __restrict__ alpha,
        const float* __restrict__ W_O,  const float* __restrict__ W_I,
        const float* __restrict__ W_S,  const float* __restrict__ W_rel,
        const int* __restrict__ dst) {
    int b = blockIdx.x;
    int tid = threadIdx.x;

    if (b > NB_PREP) {
        // ---- hist: 4 edges per thread, loads batched before atomics ----
        int e = (b - NB_PREP - 1) * 1024 + tid;
        int d0 = (e < N_EDGES) ? dst[e] : -1;
        int d1 = (e + 256 < N_EDGES) ? dst[e + 256] : -1;
        int d2 = (e + 512 < N_EDGES) ? dst[e + 512] : -1;
        int d3 = (e + 768 < N_EDGES) ? dst[e + 768] : -1;
        if (d0 >= 0) atomicAdd(&g_counts[d0], 1);
        if (d1 >= 0) atomicAdd(&g_counts[d1], 1);
        if (d2 >= 0) atomicAdd(&g_counts[d2], 1);
        if (d3 >= 0) atomicAdd(&g_counts[d3], 1);
        return;
    }
    if (b >= 1) {
        // block 1 also resets lookback flags for this replay
        if (b == 1 && tid < 128) g_flags[tid] = 0;
        // ---- prep_b: fp32 -> fp16 mma-fragment table ----
        int idx = (b - 1) * 256 + tid;
        if (idx >= N_LAYERS * BH2L) return;
        int l = idx / BH2L;
        int s = idx % BH2L;
        int r = s & 1;
        int lane = (s >> 1) & 31;
        int k16 = (s >> 6) & 3;
        int ng = s >> 8;
        int n = ng * 8 + (lane >> 2);
        int k = k16 * 16 + (lane & 3) * 2 + r * 8;
        const float* W = (n < 64) ? W_O : (n < 128) ? W_I : W_S;
        const float* row = W + l * D * D + (n & 63) * D;
        g_Bh[idx] = pkh2(row[k], row[k + 1]);
        return;
    }

    // ---- rel (block 0 only) ----
    __shared__ float sW[2][D * WPAD];
    __shared__ float hr[3][D];
    __shared__ float nhr[3][D];
    int t = tid >> 6;
    int d = tid & 63;

    if (t < 3) {
        float s = 0.f;
        #pragma unroll
        for (int bb = 0; bb < 16; bb++) s += alpha[t * 16 + bb] * Basis[bb * D + d];
        hr[t][d] = s;
    }
    __syncthreads();

    for (int l = 0; l < N_LAYERS; l++) {
        {
            const float4* A = reinterpret_cast<const float4*>(W_O + l * D * D);
            const float4* B = reinterpret_cast<const float4*>(W_I + l * D * D);
            #pragma unroll
            for (int i = 0; i < 4; i++) {
                int idx = tid + i * 256;
                int row = idx >> 4, q = idx & 15;
                float4 a = A[idx], bv = B[idx];
                float* pa = &sW[0][row * WPAD + q * 4];
                float* pb = &sW[1][row * WPAD + q * 4];
                pa[0] = a.x; pa[1] = a.y; pa[2] = a.z; pa[3] = a.w;
                pb[0] = bv.x; pb[1] = bv.y; pb[2] = bv.z; pb[3] = bv.w;
            }
        }
        __syncthreads();
        if (t < 2) {
            float so = 0.f, si = 0.f;
            #pragma unroll
            for (int k = 0; k < D; k++) {
                float hk = hr[t][k];
                so += hk * sW[0][d * WPAD + k];
                si += hk * sW[1][d * WPAD + k];
            }
            g_rO[l][t][d] = so;
            g_rI[l][t][d] = si;
        }
        __syncthreads();
        {
            const float4* A = reinterpret_cast<const float4*>(W_S + l * D * D);
            const float4* B = reinterpret_cast<const float4*>(W_rel + l * D * D);
            #pragma unroll
            for (int i = 0; i < 4; i++) {
                int idx = tid + i * 256;
                int row = idx >> 4, q = idx & 15;
                float4 a = A[idx], bv = B[idx];
                float* pa = &sW[0][row * WPAD + q * 4];
                float* pb = &sW[1][row * WPAD + q * 4];
                pa[0] = a.x; pa[1] = a.y; pa[2] = a.z; pa[3] = a.w;
                pb[0] = bv.x; pb[1] = bv.y; pb[2] = bv.z; pb[3] = bv.w;
            }
        }
        __syncthreads();
        if (t == 3) {
            float ss = 0.f;
            #pragma unroll
            for (int k = 0; k < D; k++) ss += hr[2][k] * sW[0][d * WPAD + k];
            g_rS[l][d] = ss;
        } else {
            float sr = 0.f;
            #pragma unroll
            for (int k = 0; k < D; k++) sr += hr[t][k] * sW[1][d * WPAD + k];
            if (l < N_LAYERS - 1) sr = fmaxf(sr, 0.f);
            nhr[t][d] = sr;
        }
        __syncthreads();
        if (t < 3) hr[t][d] = nhr[t][d];
        __syncthreads();
    }
}

// ---------------- fused single-pass scan (decoupled lookback) + layer-0 transform
#define NB_SCANA 98
__global__ void __launch_bounds__(256) scanA_t0_kernel(const float* __restrict__ h) {
    __shared__ __align__(16) unsigned char smem_raw[64 * SH2W2 * 4];  // 13.3 KB
    int b = blockIdx.x;
    int tid = threadIdx.x;
    if (b < NB_SCANA) {
        int* sm = reinterpret_cast<int*>(smem_raw);
        int* ws = sm;            // 8 warp-inclusive sums
        int* partial = sm + 8;   // 8 lookback partials
        int lane = tid & 31, wid = tid >> 5;
        int base = b * 1024 + tid * 4;
        int v[4];
        #pragma unroll
        for (int j = 0; j < 4; j++) {
            int idx = base + j;
            v[j] = 0;
            if (idx < N_NODES) { v[j] = g_counts[idx]; g_counts[idx] = 0; }
        }
        int s[4];
        s[0] = v[0]; s[1] = s[0] + v[1]; s[2] = s[1] + v[2]; s[3] = s[2] + v[3];
        int t = s[3];
        int inc = t;
        #pragma unroll
        for (int o = 1; o < 32; o <<= 1) {
            int x = __shfl_up_sync(0xffffffffu, inc, o);
            if (lane >= o) inc += x;
        }
        if (lane == 31) ws[wid] = inc;
        __syncthreads();
        if (wid == 0) {
            int wv = (lane < 8) ? ws[lane] : 0;
            int winc = wv;
            #pragma unroll
            for (int o = 1; o < 8; o <<= 1) {
                int x = __shfl_up_sync(0xffffffffu, winc, o);
                if (lane >= o) winc += x;
            }
            if (lane < 8) ws[lane] = winc;   // inclusive warp sums
        }
        __syncthreads();
        // publish block total ASAP (release: fence then flag)
        if (tid == 0) {
            g_blockSums[b] = ws[7];
            __threadfence();
            *((volatile int*)&g_flags[b]) = 1;
        }
        int wexcl = (wid > 0) ? ws[wid - 1] : 0;
        int texcl = wexcl + inc - t;
        // decoupled lookback: thread p (< b) waits for block p's sum
        int myv = 0;
        if (tid < b) {
            volatile int* vf = (volatile int*)g_flags;
            while (vf[tid] == 0) {}
            __threadfence();
            myv = g_blockSums[tid];
        }
        #pragma unroll
        for (int o = 16; o > 0; o >>= 1) myv += __shfl_down_sync(0xffffffffu, myv, o);
        if (lane == 0) partial[wid] = myv;
        __syncthreads();
        if (wid == 0) {
            int x = (lane < 8) ? partial[lane] : 0;
            #pragma unroll
            for (int o = 4; o > 0; o >>= 1) x += __shfl_down_sync(0xffffffffu, x, o);
            if (lane == 0) partial[0] = x;
        }
        __syncthreads();
        int off = partial[0];
        #pragma unroll
        for (int j = 0; j < 4; j++) {
            int idx = base + j;
            if (idx < N_NODES) {
                int val = off + texcl + (j > 0 ? s[j - 1] : 0);
                g_indptr[idx] = val;
                g_cursor[idx] = val;
            }
        }
        if (b == 0 && tid == 0) g_indptr[N_NODES] = N_EDGES;
        return;
    }
    transform_tile(h, 0, b - NB_SCANA, smem_raw);
}

// ---------------- fill: 4 edges/thread; records pre-decoded for aggregation ------
// rec = (src + dir*N) | (cat*8 << 18), cat = et + dir*2
__global__ void __launch_bounds__(256) fill_kernel(const int* __restrict__ src,
                                                   const int* __restrict__ dst,
                                                   const int* __restrict__ et,
                                                   const int* __restrict__ dir) {
    int base = blockIdx.x * 1024 + threadIdx.x;
    int e0 = base, e1 = base + 256, e2 = base + 512, e3 = base + 768;
    int d0 = (e0 < N_EDGES) ? dst[e0] : -1;
    int d1 = (e1 < N_EDGES) ? dst[e1] : -1;
    int d2 = (e2 < N_EDGES) ? dst[e2] : -1;
    int d3 = (e3 < N_EDGES) ? dst[e3] : -1;
    int r0 = 0, r1 = 0, r2 = 0, r3 = 0;
    if (d0 >= 0) r0 = (src[e0] + dir[e0] * N_NODES) | ((et[e0] + dir[e0] * 2) << 21);
    if (d1 >= 0) r1 = (src[e1] + dir[e1] * N_NODES) | ((et[e1] + dir[e1] * 2) << 21);
    if (d2 >= 0) r2 = (src[e2] + dir[e2] * N_NODES) | ((et[e2] + dir[e2] * 2) << 21);
    if (d3 >= 0) r3 = (src[e3] + dir[e3] * N_NODES) | ((et[e3] + dir[e3] * 2) << 21);
    int p0 = (d0 >= 0) ? atomicAdd(&g_cursor[d0], 1) : 0;
    int p1 = (d1 >= 0) ? atomicAdd(&g_cursor[d1], 1) : 0;
    int p2 = (d2 >= 0) ? atomicAdd(&g_cursor[d2], 1) : 0;
    int p3 = (d3 >= 0) ? atomicAdd(&g_cursor[d3], 1) : 0;
    if (d0 >= 0) g_recs[p0] = r0;
    if (d1 >= 0) g_recs[p1] = r1;
    if (d2 >= 0) g_recs[p2] = r2;
    if (d3 >= 0) g_recs[p3] = r3;
}

// ---------------- standalone transform (layers 1,2) ------------------------------
__global__ void __launch_bounds__(256) transform_kernel(const float* __restrict__ h,
                                                        int layer) {
    __shared__ __align__(16) unsigned char smem_raw[64 * SH2W2 * 4];  // 13.3 KB
    transform_tile(h, layer, blockIdx.x, smem_raw);
}

// ---------------- aggregation: warp/node, 16-lane sub-warps, LDG.64 gathers ------
// Lanes 0-15 process even-position edges, 16-31 odd ones; each lane covers 4
// consecutive halves (8B) of the row. Records pre-decoded: row = rec & 0x3FFFF,
// cnt shift = rec >> 18.
__global__ void __launch_bounds__(256) aggregate_kernel(int l, float* __restrict__ hout,
                                                        int do_relu) {
    int warp = (blockIdx.x * blockDim.x + threadIdx.x) >> 5;
    int lane = threadIdx.x & 31;
    if (warp >= N_NODES) return;
    int v = warp;
    int half = lane >> 4;
    int sl = lane & 15;

    const uint2* __restrict__ X = reinterpret_cast<const uint2*>(&g_Xh[0][0]);

    float4 acc = make_float4(0.f, 0.f, 0.f, 0.f);
    if (half == 0) {
        uint2 xs = X[((size_t)2 * N_NODES + v) * 16 + sl];
        float2 a = h2f2(xs.x), b = h2f2(xs.y);
        acc = make_float4(a.x, a.y, b.x, b.y);
    }

    int beg = g_indptr[v], end = g_indptr[v + 1];
    unsigned cnt = 0;
    int i = beg;
    for (; i + 7 < end; i += 8) {
        int r0 = g_recs[i + half];
        int r1 = g_recs[i + 2 + half];
        int r2 = g_recs[i + 4 + half];
        int r3 = g_recs[i + 6 + half];
        uint2 m0 = X[(size_t)(r0 & 0x3FFFF) * 16 + sl];
        uint2 m1 = X[(size_t)(r1 & 0x3FFFF) * 16 + sl];
        uint2 m2 = X[(size_t)(r2 & 0x3FFFF) * 16 + sl];
        uint2 m3 = X[(size_t)(r3 & 0x3FFFF) * 16 + sl];
        cnt += (1u << (r0 >> 18)) + (1u << (r1 >> 18));
        cnt += (1u << (r2 >> 18)) + (1u << (r3 >> 18));
        float2 a;
        a = h2f2(m0.x); acc.x += a.x; acc.y += a.y;
        a = h2f2(m0.y); acc.z += a.x; acc.w += a.y;
        a = h2f2(m1.x); acc.x += a.x; acc.y += a.y;
        a = h2f2(m1.y); acc.z += a.x; acc.w += a.y;
        a = h2f2(m2.x); acc.x += a.x; acc.y += a.y;
        a = h2f2(m2.y); acc.z += a.x; acc.w += a.y;
        a = h2f2(m3.x); acc.x += a.x; acc.y += a.y;
        a = h2f2(m3.y); acc.z += a.x; acc.w += a.y;
    }
    for (; i < end; i += 2) {
        int e = i + half;
        if (e < end) {
            int r = g_recs[e];
            uint2 m = X[(size_t)(r & 0x3FFFF) * 16 + sl];
            cnt += 1u << (r >> 18);
            float2 a = h2f2(m.x); acc.x += a.x; acc.y += a.y;
            a = h2f2(m.y); acc.z += a.x; acc.w += a.y;
        }
    }

    // combine the two halves (lane L gets lane L+16's partials)
    acc.x += __shfl_down_sync(0xffffffffu, acc.x, 16);
    acc.y += __shfl_down_sync(0xffffffffu, acc.y, 16);
    acc.z += __shfl_down_sync(0xffffffffu, acc.z, 16);
    acc.w += __shfl_down_sync(0xffffffffu, acc.w, 16);
    cnt   += __shfl_down_sync(0xffffffffu, cnt, 16);

    if (half == 0) {
        float4 ro0 = reinterpret_cast<const float4*>(g_rO[l][0])[sl];
        float4 ro1 = reinterpret_cast<const float4*>(g_rO[l][1])[sl];
        float4 ri0 = reinterpret_cast<const float4*>(g_rI[l][0])[sl];
        float4 ri1 = reinterpret_cast<const float4*>(g_rI[l][1])[sl];
        float4 rs  = reinterpret_cast<const float4*>(g_rS[l])[sl];
        float n0 = (float)(cnt & 255u);
        float n1 = (float)((cnt >> 8) & 255u);
        float n2 = (float)((cnt >> 16) & 255u);
        float n3 = (float)((cnt >> 24) & 255u);
        acc.x -= n0 * ro0.x + n1 * ro1.x + n2 * ri0.x + n3 * ri1.x + rs.x;
        acc.y -= n0 * ro0.y + n1 * ro1.y + n2 * ri0.y + n3 * ri1.y + rs.y;
        acc.z -= n0 * ro0.z + n1 * ro1.z + n2 * ri0.z + n3 * ri1.z + rs.z;
        acc.w -= n0 * ro0.w + n1 * ro1.w + n2 * ri0.w + n3 * ri1.w + rs.w;
        if (do_relu) {
            acc.x = fmaxf(acc.x, 0.f); acc.y = fmaxf(acc.y, 0.f);
            acc.z = fmaxf(acc.z, 0.f); acc.w = fmaxf(acc.w, 0.f);
        }
        reinterpret_cast<float4*>(hout)[(size_t)v * 16 + sl] = acc;
    }
}

// ---------------- launch ----------------
extern "C" void kernel_launch(void* const* d_in, const int* in_sizes, int n_in,
                              void* d_out, int out_size) {
    const float* h_u   = (const float*)d_in[0];
    const float* Basis = (const float*)d_in[1];
    const float* alpha = (const float*)d_in[2];
    const float* W_O   = (const float*)d_in[3];
    const float* W_I   = (const float*)d_in[4];
    const float* W_S   = (const float*)d_in[5];
    const float* W_rel = (const float*)d_in[6];
    const int*   src   = (const int*)d_in[7];
    const int*   dst   = (const int*)d_in[8];
    const int*   et    = (const int*)d_in[9];
    const int*   dir   = (const int*)d_in[10];
    float* out = (float*)d_out;

    void* ph = nullptr;
    cudaGetSymbolAddress(&ph, g_h);
    float* h0 = (float*)ph;
    float* h1 = h0 + (size_t)N_NODES * D;

    int nb_transform = ((N_NODES + 63) / 64) * 2;

    // 1: fused rel + weight-prep + degree-histogram (+ flag reset)
    setup_kernel<<<1 + NB_PREP + NB_HIST, 256>>>(Basis, alpha, W_O, W_I, W_S,
                                                 W_rel, dst);
    // 2: single-pass scan (lookback) fused with layer-0 transform
    scanA_t0_kernel<<<NB_SCANA + nb_transform, 256>>>(h_u);
    // 3: CSR fill
    fill_kernel<<<(N_EDGES + 1023) / 1024, 256>>>(src, dst, et, dir);

    for (int l = 0; l < N_LAYERS; l++) {
        if (l > 0) {
            const float* hin = (l == 1) ? h0 : h1;
            transform_kernel<<<nb_transform, 256>>>(hin, l);
        }
        float* hout = (l == N_LAYERS - 1) ? out : (l == 0 ? h0 : h1);
        int do_relu = (l < N_LAYERS - 1) ? 1 : 0;
        aggregate_kernel<<<(N_NODES * 32 + 255) / 256, 256>>>(l, hout, do_relu);
    }
}

// round 17
// speedup vs baseline: 1.0570x; 1.0173x over previous
#include <cuda_runtime.h>
#include <cuda_fp16.h>
#include <cstdint>

#define N_NODES 100000
#define N_EDGES 1200000
#define D 64
#define N_LAYERS 3
#define BN 192   // fused output cols: W_O | W_I | W_S
#define NG (BN / 8)              // 24 column-groups of 8
#define BH2L (NG * 4 * 32 * 2)   // 6144 half2 words per layer (fp16 B table)

// ---------------- scratch (static device globals; no allocation) ----------------
__device__ __half g_Xh[3][(size_t)N_NODES * D];   // Xo, Xi, Xs (fp16)
__device__ float g_h[2][(size_t)N_NODES * D];     // ping-pong hidden states
__device__ int   g_counts[N_NODES];               // zero at load; re-zeroed by scan
__device__ int   g_indptr[N_NODES + 1];
__device__ int   g_cursor[N_NODES];
__device__ int   g_recs[N_EDGES];   // packed: (src + dir*N) | cat<<21 ; cat=et+2*dir
__device__ int   g_blockSums[128];
__device__ int   g_flags[128];                  // lookback flags; reset by setup
__device__ int   g_scanDone;                    // scan completion counter
__device__ unsigned g_Bh[N_LAYERS * BH2L];      // fp16 weights, mma-fragment-major
__device__ float g_rO[N_LAYERS][2][D];
__device__ float g_rI[N_LAYERS][2][D];
__device__ float g_rS[N_LAYERS][D];

// ---------------- helpers ----------------
__device__ __forceinline__ unsigned pkh2(float a, float b) {
    __half2 h = __floats2half2_rn(a, b);
    return *reinterpret_cast<unsigned*>(&h);
}
__device__ __forceinline__ void mma_f16(float c[4], unsigned a0, unsigned a1,
                                        unsigned a2, unsigned a3,
                                        unsigned b0, unsigned b1) {
    asm("mma.sync.aligned.m16n8k16.row.col.f32.f16.f16.f32 "
        "{%0,%1,%2,%3}, {%4,%5,%6,%7}, {%8,%9}, {%0,%1,%2,%3};"
        : "+f"(c[0]), "+f"(c[1]), "+f"(c[2]), "+f"(c[3])
        : "r"(a0), "r"(a1), "r"(a2), "r"(a3), "r"(b0), "r"(b1));
}
__device__ __forceinline__ float2 h2f2(unsigned u) {
    __half2 h = *reinterpret_cast<__half2*>(&u);
    return __half22float2(h);
}

// ---------------- transform tile body ----------------
#define SH2W2 52   // half2 words per smem row in epilogue view (48 data + 4 pad)
__device__ __forceinline__ void transform_tile(const float* __restrict__ h,
                                               int layer, int tb,
                                               unsigned char* smem_raw) {
    uint4* sAu4 = reinterpret_cast<uint4*>(smem_raw);      // [16 tiles][33] A frag
    unsigned* sw = reinterpret_cast<unsigned*>(smem_raw);  // word view
    unsigned* sh2 = reinterpret_cast<unsigned*>(smem_raw); // epilogue half2 view

    int tid = threadIdx.x;
    int wid = tid >> 5, lane = tid & 31;
    int gid = lane >> 2, tig = lane & 3;
    int wm = wid & 1, wn = wid >> 1;
    int nh = tb & 1;
    size_t rowbase = (size_t)(tb >> 1) * 64;

    // stage A: coalesced float4 LDG -> fp16 fragment smem
    #pragma unroll
    for (int i = 0; i < 4; i++) {
        int idx = tid + i * 256;          // over 1024 float4 (64 rows x 16)
        int row = idx >> 4, q = idx & 15;
        size_t gr = rowbase + row;
        float4 x = make_float4(0.f, 0.f, 0.f, 0.f);
        if (gr < N_NODES) x = reinterpret_cast<const float4*>(h + gr * D)[q];
        int k16 = q >> 2;
        int tg  = (q << 1) & 3;
        int kh  = (q >> 1) & 1;
        int L   = (row & 7) * 4 + tg;
        int r   = ((row >> 3) & 1) + kh * 2;
        int t   = (row >> 4) * 4 + k16;
        unsigned w = (unsigned)(t * 33 + L) * 4 + r;
        sw[w]     = pkh2(x.x, x.y);
        sw[w + 4] = pkh2(x.z, x.w);
    }
    __syncthreads();

    const uint2* __restrict__ Bh =
        reinterpret_cast<const uint2*>(g_Bh) + (size_t)layer * (BH2L / 2);
    float acc[2][3][4];
    #pragma unroll
    for (int mt = 0; mt < 2; mt++)
        #pragma unroll
        for (int nt = 0; nt < 3; nt++)
            #pragma unroll
            for (int q = 0; q < 4; q++) acc[mt][nt][q] = 0.f;

    #pragma unroll
    for (int k16 = 0; k16 < 4; k16++) {
        uint4 a0 = sAu4[(((wm * 2 + 0) * 4 + k16) * 33) + lane];
        uint4 a1 = sAu4[(((wm * 2 + 1) * 4 + k16) * 33) + lane];
        #pragma unroll
        for (int nt = 0; nt < 3; nt++) {
            int ng = nh * 12 + wn * 3 + nt;
            uint2 b = Bh[((ng * 4 + k16) * 32) + lane];
            mma_f16(acc[0][nt], a0.x, a0.y, a0.z, a0.w, b.x, b.y);
            mma_f16(acc[1][nt], a1.x, a1.y, a1.z, a1.w, b.x, b.y);
        }
    }
    __syncthreads();   // mainloop smem reads done before epilogue reuse

    // epilogue pass 1: acc fragments -> half2 smem (stride 52: conflict-free)
    #pragma unroll
    for (int mt = 0; mt < 2; mt++) {
        #pragma unroll
        for (int half = 0; half < 2; half++) {
            int row = wm * 32 + mt * 16 + half * 8 + gid;
            #pragma unroll
            for (int nt = 0; nt < 3; nt++) {
                int col2 = wn * 12 + nt * 4 + tig;
                float lo = half ? acc[mt][nt][2] : acc[mt][nt][0];
                float hi = half ? acc[mt][nt][3] : acc[mt][nt][1];
                sh2[row * SH2W2 + col2] = pkh2(lo, hi);
            }
        }
    }
    __syncthreads();

    // epilogue pass 2: coalesced STG.128 (8 halves each) to g_Xh
    #pragma unroll
    for (int i = 0; i < 3; i++) {
        int o = tid + i * 256;            // over 768 uint4 slots (64 rows x 12)
        int r = o / 12;
        int q = o % 12;
        size_t gr = rowbase + r;
        if (gr < N_NODES) {
            int c0 = nh * 96 + q * 8;
            int mat = c0 >> 6, cc = c0 & 63;
            uint4 val = *reinterpret_cast<const uint4*>(&sh2[r * SH2W2 + q * 4]);
            *reinterpret_cast<uint4*>(&g_Xh[mat][gr * D + cc]) = val;
        }
    }
}

// ---------------- fused setup: rel (block 0) + prep_b (1..72) + hist (73..) -----
#define WPAD 65
#define NB_PREP 72
#define NB_HIST ((N_EDGES + 1023) / 1024)
__global__ void __launch_bounds__(256) setup_kernel(
        const float* __restrict__ Basis, const float* __restrict__ alpha,
        const float* __restrict__ W_O,  const float* __restrict__ W_I,
        const float* __restrict__ W_S,  const float* __restrict__ W_rel,
        const int* __restrict__ dst) {
    int b = blockIdx.x;
    int tid = threadIdx.x;

    if (b > NB_PREP) {
        // ---- hist: 4 edges per thread, loads batched before atomics ----
        int e = (b - NB_PREP - 1) * 1024 + tid;
        int d0 = (e < N_EDGES) ? dst[e] : -1;
        int d1 = (e + 256 < N_EDGES) ? dst[e + 256] : -1;
        int d2 = (e + 512 < N_EDGES) ? dst[e + 512] : -1;
        int d3 = (e + 768 < N_EDGES) ? dst[e + 768] : -1;
        if (d0 >= 0) atomicAdd(&g_counts[d0], 1);
        if (d1 >= 0) atomicAdd(&g_counts[d1], 1);
        if (d2 >= 0) atomicAdd(&g_counts[d2], 1);
        if (d3 >= 0) atomicAdd(&g_counts[d3], 1);
        return;
    }
    if (b >= 1) {
        // block 1 also resets lookback flags + scan-done counter for this replay
        if (b == 1 && tid < 128) g_flags[tid] = 0;
        if (b == 1 && tid == 128) g_scanDone = 0;
        // ---- prep_b: fp32 -> fp16 mma-fragment table ----
        int idx = (b - 1) * 256 + tid;
        if (idx >= N_LAYERS * BH2L) return;
        int l = idx / BH2L;
        int s = idx % BH2L;
        int r = s & 1;
        int lane = (s >> 1) & 31;
        int k16 = (s >> 6) & 3;
        int ng = s >> 8;
        int n = ng * 8 + (lane >> 2);
        int k = k16 * 16 + (lane & 3) * 2 + r * 8;
        const float* W = (n < 64) ? W_O : (n < 128) ? W_I : W_S;
        const float* row = W + l * D * D + (n & 63) * D;
        g_Bh[idx] = pkh2(row[k], row[k + 1]);
        return;
    }

    // ---- rel (block 0 only) ----
    __shared__ float sW[2][D * WPAD];
    __shared__ float hr[3][D];
    __shared__ float nhr[3][D];
    int t = tid >> 6;
    int d = tid & 63;

    if (t < 3) {
        float s = 0.f;
        #pragma unroll
        for (int bb = 0; bb < 16; bb++) s += alpha[t * 16 + bb] * Basis[bb * D + d];
        hr[t][d] = s;
    }
    __syncthreads();

    for (int l = 0; l < N_LAYERS; l++) {
        {
            const float4* A = reinterpret_cast<const float4*>(W_O + l * D * D);
            const float4* B = reinterpret_cast<const float4*>(W_I + l * D * D);
            #pragma unroll
            for (int i = 0; i < 4; i++) {
                int idx = tid + i * 256;
                int row = idx >> 4, q = idx & 15;
                float4 a = A[idx], bv = B[idx];
                float* pa = &sW[0][row * WPAD + q * 4];
                float* pb = &sW[1][row * WPAD + q * 4];
                pa[0] = a.x; pa[1] = a.y; pa[2] = a.z; pa[3] = a.w;
                pb[0] = bv.x; pb[1] = bv.y; pb[2] = bv.z; pb[3] = bv.w;
            }
        }
        __syncthreads();
        if (t < 2) {
            float so = 0.f, si = 0.f;
            #pragma unroll
            for (int k = 0; k < D; k++) {
                float hk = hr[t][k];
                so += hk * sW[0][d * WPAD + k];
                si += hk * sW[1][d * WPAD + k];
            }
            g_rO[l][t][d] = so;
            g_rI[l][t][d] = si;
        }
        __syncthreads();
        {
            const float4* A = reinterpret_cast<const float4*>(W_S + l * D * D);
            const float4* B = reinterpret_cast<const float4*>(W_rel + l * D * D);
            #pragma unroll
            for (int i = 0; i < 4; i++) {
                int idx = tid + i * 256;
                int row = idx >> 4, q = idx & 15;
                float4 a = A[idx], bv = B[idx];
                float* pa = &sW[0][row * WPAD + q * 4];
                float* pb = &sW[1][row * WPAD + q * 4];
                pa[0] = a.x; pa[1] = a.y; pa[2] = a.z; pa[3] = a.w;
                pb[0] = bv.x; pb[1] = bv.y; pb[2] = bv.z; pb[3] = bv.w;
            }
        }
        __syncthreads();
        if (t == 3) {
            float ss = 0.f;
            #pragma unroll
            for (int k = 0; k < D; k++) ss += hr[2][k] * sW[0][d * WPAD + k];
            g_rS[l][d] = ss;
        } else {
            float sr = 0.f;
            #pragma unroll
            for (int k = 0; k < D; k++) sr += hr[t][k] * sW[1][d * WPAD + k];
            if (l < N_LAYERS - 1) sr = fmaxf(sr, 0.f);
            nhr[t][d] = sr;
        }
        __syncthreads();
        if (t < 3) hr[t][d] = nhr[t][d];
        __syncthreads();
    }
}

// ---------------- fused: scan (lookback) + layer-0 transform + fill --------------
// blocks [0,98): scan, publish final indptr/cursor, then bump g_scanDone.
// blocks [98, 98+nbT): layer-0 transform tiles.
// blocks [98+nbT, ...): CSR fill — spin until g_scanDone==98 (grid-tail blocks,
// so the spin exits immediately; scan blocks are wave-1 resident => no deadlock).
#define NB_SCANA 98
#define NB_FILLB ((N_EDGES + 1023) / 1024)
__global__ void __launch_bounds__(256) scan_t0_fill_kernel(
        const float* __restrict__ h,
        const int* __restrict__ src, const int* __restrict__ dst,
        const int* __restrict__ et,  const int* __restrict__ dir,
        int nbT) {
    __shared__ __align__(16) unsigned char smem_raw[64 * SH2W2 * 4];  // 13.3 KB
    int b = blockIdx.x;
    int tid = threadIdx.x;
    if (b < NB_SCANA) {
        int* sm = reinterpret_cast<int*>(smem_raw);
        int* ws = sm;            // 8 warp-inclusive sums
        int* partial = sm + 8;   // 8 lookback partials
        int lane = tid & 31, wid = tid >> 5;
        int base = b * 1024 + tid * 4;
        int v[4];
        #pragma unroll
        for (int j = 0; j < 4; j++) {
            int idx = base + j;
            v[j] = 0;
            if (idx < N_NODES) { v[j] = g_counts[idx]; g_counts[idx] = 0; }
        }
        int s[4];
        s[0] = v[0]; s[1] = s[0] + v[1]; s[2] = s[1] + v[2]; s[3] = s[2] + v[3];
        int t = s[3];
        int inc = t;
        #pragma unroll
        for (int o = 1; o < 32; o <<= 1) {
            int x = __shfl_up_sync(0xffffffffu, inc, o);
            if (lane >= o) inc += x;
        }
        if (lane == 31) ws[wid] = inc;
        __syncthreads();
        if (wid == 0) {
            int wv = (lane < 8) ? ws[lane] : 0;
            int winc = wv;
            #pragma unroll
            for (int o = 1; o < 8; o <<= 1) {
                int x = __shfl_up_sync(0xffffffffu, winc, o);
                if (lane >= o) winc += x;
            }
            if (lane < 8) ws[lane] = winc;   // inclusive warp sums
        }
        __syncthreads();
        // publish block total ASAP (release: fence then flag)
        if (tid == 0) {
            g_blockSums[b] = ws[7];
            __threadfence();
            *((volatile int*)&g_flags[b]) = 1;
        }
        int wexcl = (wid > 0) ? ws[wid - 1] : 0;
        int texcl = wexcl + inc - t;
        // decoupled lookback: thread p (< b) waits for block p's sum
        int myv = 0;
        if (tid < b) {
            volatile int* vf = (volatile int*)g_flags;
            while (vf[tid] == 0) {}
            __threadfence();
            myv = g_blockSums[tid];
        }
        #pragma unroll
        for (int o = 16; o > 0; o >>= 1) myv += __shfl_down_sync(0xffffffffu, myv, o);
        if (lane == 0) partial[wid] = myv;
        __syncthreads();
        if (wid == 0) {
            int x = (lane < 8) ? partial[lane] : 0;
            #pragma unroll
            for (int o = 4; o > 0; o >>= 1) x += __shfl_down_sync(0xffffffffu, x, o);
            if (lane == 0) partial[0] = x;
        }
        __syncthreads();
        int off = partial[0];
        #pragma unroll
        for (int j = 0; j < 4; j++) {
            int idx = base + j;
            if (idx < N_NODES) {
                int val = off + texcl + (j > 0 ? s[j - 1] : 0);
                g_indptr[idx] = val;
                g_cursor[idx] = val;
            }
        }
        if (b == 0 && tid == 0) g_indptr[N_NODES] = N_EDGES;
        // signal completion (threadFenceReduction pattern)
        __threadfence();
        __syncthreads();
        if (tid == 0) atomicAdd(&g_scanDone, 1);
        return;
    }
    if (b < NB_SCANA + nbT) {
        transform_tile(h, 0, b - NB_SCANA, smem_raw);
        return;
    }
    // ---- fill range: wait for all scan blocks, then fill ----
    if (tid == 0) {
        volatile int* vd = (volatile int*)&g_scanDone;
        while (*vd < NB_SCANA) {}
    }
    __syncthreads();
    __threadfence();
    int fb = b - NB_SCANA - nbT;
    int base = fb * 1024 + tid;
    int e0 = base, e1 = base + 256, e2 = base + 512, e3 = base + 768;
    int d0 = (e0 < N_EDGES) ? dst[e0] : -1;
    int d1 = (e1 < N_EDGES) ? dst[e1] : -1;
    int d2 = (e2 < N_EDGES) ? dst[e2] : -1;
    int d3 = (e3 < N_EDGES) ? dst[e3] : -1;
    int r0 = 0, r1 = 0, r2 = 0, r3 = 0;
    if (d0 >= 0) r0 = (src[e0] + dir[e0] * N_NODES) | ((et[e0] + dir[e0] * 2) << 21);
    if (d1 >= 0) r1 = (src[e1] + dir[e1] * N_NODES) | ((et[e1] + dir[e1] * 2) << 21);
    if (d2 >= 0) r2 = (src[e2] + dir[e2] * N_NODES) | ((et[e2] + dir[e2] * 2) << 21);
    if (d3 >= 0) r3 = (src[e3] + dir[e3] * N_NODES) | ((et[e3] + dir[e3] * 2) << 21);
    int p0 = (d0 >= 0) ? atomicAdd(&g_cursor[d0], 1) : 0;
    int p1 = (d1 >= 0) ? atomicAdd(&g_cursor[d1], 1) : 0;
    int p2 = (d2 >= 0) ? atomicAdd(&g_cursor[d2], 1) : 0;
    int p3 = (d3 >= 0) ? atomicAdd(&g_cursor[d3], 1) : 0;
    if (d0 >= 0) g_recs[p0] = r0;
    if (d1 >= 0) g_recs[p1] = r1;
    if (d2 >= 0) g_recs[p2] = r2;
    if (d3 >= 0) g_recs[p3] = r3;
}

// ---------------- standalone transform (layers 1,2) ------------------------------
__global__ void __launch_bounds__(256) transform_kernel(const float* __restrict__ h,
                                                        int layer) {
    __shared__ __align__(16) unsigned char smem_raw[64 * SH2W2 * 4];  // 13.3 KB
    transform_tile(h, layer, blockIdx.x, smem_raw);
}

// ---------------- aggregation: warp/node, 16-lane sub-warps, LDG.64 gathers ------
__global__ void __launch_bounds__(256) aggregate_kernel(int l, float* __restrict__ hout,
                                                        int do_relu) {
    int warp = (blockIdx.x * blockDim.x + threadIdx.x) >> 5;
    int lane = threadIdx.x & 31;
    if (warp >= N_NODES) return;
    int v = warp;
    int half = lane >> 4;
    int sl = lane & 15;

    const uint2* __restrict__ X = reinterpret_cast<const uint2*>(&g_Xh[0][0]);

    float4 acc = make_float4(0.f, 0.f, 0.f, 0.f);
    if (half == 0) {
        uint2 xs = X[((size_t)2 * N_NODES + v) * 16 + sl];
        float2 a = h2f2(xs.x), b = h2f2(xs.y);
        acc = make_float4(a.x, a.y, b.x, b.y);
    }

    int beg = g_indptr[v], end = g_indptr[v + 1];
    unsigned cnt = 0;
    int i = beg;
    for (; i + 7 < end; i += 8) {
        int r0 = g_recs[i + half];
        int r1 = g_recs[i + 2 + half];
        int r2 = g_recs[i + 4 + half];
        int r3 = g_recs[i + 6 + half];
        uint2 m0 = X[(size_t)(r0 & 0x3FFFF) * 16 + sl];
        uint2 m1 = X[(size_t)(r1 & 0x3FFFF) * 16 + sl];
        uint2 m2 = X[(size_t)(r2 & 0x3FFFF) * 16 + sl];
        uint2 m3 = X[(size_t)(r3 & 0x3FFFF) * 16 + sl];
        cnt += (1u << (r0 >> 18)) + (1u << (r1 >> 18));
        cnt += (1u << (r2 >> 18)) + (1u << (r3 >> 18));
        float2 a;
        a = h2f2(m0.x); acc.x += a.x; acc.y += a.y;
        a = h2f2(m0.y); acc.z += a.x; acc.w += a.y;
        a = h2f2(m1.x); acc.x += a.x; acc.y += a.y;
        a = h2f2(m1.y); acc.z += a.x; acc.w += a.y;
        a = h2f2(m2.x); acc.x += a.x; acc.y += a.y;
        a = h2f2(m2.y); acc.z += a.x; acc.w += a.y;
        a = h2f2(m3.x); acc.x += a.x; acc.y += a.y;
        a = h2f2(m3.y); acc.z += a.x; acc.w += a.y;
    }
    for (; i < end; i += 2) {
        int e = i + half;
        if (e < end) {
            int r = g_recs[e];
            uint2 m = X[(size_t)(r & 0x3FFFF) * 16 + sl];
            cnt += 1u << (r >> 18);
            float2 a = h2f2(m.x); acc.x += a.x; acc.y += a.y;
            a = h2f2(m.y); acc.z += a.x; acc.w += a.y;
        }
    }

    // combine the two halves (lane L gets lane L+16's partials)
    acc.x += __shfl_down_sync(0xffffffffu, acc.x, 16);
    acc.y += __shfl_down_sync(0xffffffffu, acc.y, 16);
    acc.z += __shfl_down_sync(0xffffffffu, acc.z, 16);
    acc.w += __shfl_down_sync(0xffffffffu, acc.w, 16);
    cnt   += __shfl_down_sync(0xffffffffu, cnt, 16);

    if (half == 0) {
        float4 ro0 = reinterpret_cast<const float4*>(g_rO[l][0])[sl];
        float4 ro1 = reinterpret_cast<const float4*>(g_rO[l][1])[sl];
        float4 ri0 = reinterpret_cast<const float4*>(g_rI[l][0])[sl];
        float4 ri1 = reinterpret_cast<const float4*>(g_rI[l][1])[sl];
        float4 rs  = reinterpret_cast<const float4*>(g_rS[l])[sl];
        float n0 = (float)(cnt & 255u);
        float n1 = (float)((cnt >> 8) & 255u);
        float n2 = (float)((cnt >> 16) & 255u);
        float n3 = (float)((cnt >> 24) & 255u);
        acc.x -= n0 * ro0.x + n1 * ro1.x + n2 * ri0.x + n3 * ri1.x + rs.x;
        acc.y -= n0 * ro0.y + n1 * ro1.y + n2 * ri0.y + n3 * ri1.y + rs.y;
        acc.z -= n0 * ro0.z + n1 * ro1.z + n2 * ri0.z + n3 * ri1.z + rs.z;
        acc.w -= n0 * ro0.w + n1 * ro1.w + n2 * ri0.w + n3 * ri1.w + rs.w;
        if (do_relu) {
            acc.x = fmaxf(acc.x, 0.f); acc.y = fmaxf(acc.y, 0.f);
            acc.z = fmaxf(acc.z, 0.f); acc.w = fmaxf(acc.w, 0.f);
        }
        reinterpret_cast<float4*>(hout)[(size_t)v * 16 + sl] = acc;
    }
}

// ---------------- launch ----------------
extern "C" void kernel_launch(void* const* d_in, const int* in_sizes, int n_in,
                              void* d_out, int out_size) {
    const float* h_u   = (const float*)d_in[0];
    const float* Basis = (const float*)d_in[1];
    const float* alpha = (const float*)d_in[2];
    const float* W_O   = (const float*)d_in[3];
    const float* W_I   = (const float*)d_in[4];
    const float* W_S   = (const float*)d_in[5];
    const float* W_rel = (const float*)d_in[6];
    const int*   src   = (const int*)d_in[7];
    const int*   dst   = (const int*)d_in[8];
    const int*   et    = (const int*)d_in[9];
    const int*   dir   = (const int*)d_in[10];
    float* out = (float*)d_out;

    void* ph = nullptr;
    cudaGetSymbolAddress(&ph, g_h);
    float* h0 = (float*)ph;
    float* h1 = h0 + (size_t)N_NODES * D;

    int nb_transform = ((N_NODES + 63) / 64) * 2;

    // 1: fused rel + weight-prep + degree-histogram (+ flag/counter reset)
    setup_kernel<<<1 + NB_PREP + NB_HIST, 256>>>(Basis, alpha, W_O, W_I, W_S,
                                                 W_rel, dst);
    // 2: single-pass scan + layer-0 transform + fill (fill gated on scan-done)
    scan_t0_fill_kernel<<<NB_SCANA + nb_transform + NB_FILLB, 256>>>(
        h_u, src, dst, et, dir, nb_transform);

    for (int l = 0; l < N_LAYERS; l++) {
        if (l > 0) {
            const float* hin = (l == 1) ? h0 : h1;
            transform_kernel<<<nb_transform, 256>>>(hin, l);
        }
        float* hout = (l == N_LAYERS - 1) ? out : (l == 0 ? h0 : h1);
        int do_relu = (l < N_LAYERS - 1) ? 1 : 0;
        aggregate_kernel<<<(N_NODES * 32 + 255) / 256, 256>>>(l, hout, do_relu);
    }
}